// round 12
// baseline (speedup 1.0000x reference)
#include <cuda_runtime.h>
#include <cuda_bf16.h>
#include <cuda_fp16.h>
#include <math.h>
#include <cstdint>

#define TT 2048
#define DIM 1024
#define NH 16
#define HD 64
#define WIN 16
#define KS 33
#define NG 32
#define NKEY (KS + NG)

// ---------------- scratch (device globals, no allocation) ----------------
__device__ float g_Q[TT * DIM];
__device__ float g_K[TT * DIM];
__device__ float g_V[TT * DIM];
__device__ __half g_xf[TT * DIM];
__device__ __half g_wf[4 * DIM * DIM];
__device__ __half g_cf[TT * DIM];

// ---------------- PTX helpers (sm_80-generic only) ----------------
__device__ __forceinline__ uint32_t s2u(const void* p) {
    uint32_t a;
    asm("{ .reg .u64 t; cvta.to.shared.u64 t, %1; cvt.u32.u64 %0, t; }" : "=r"(a) : "l"(p));
    return a;
}
__device__ __forceinline__ void cp16(uint32_t saddr, const void* g) {
    asm volatile("cp.async.cg.shared.global [%0], [%1], 16;" :: "r"(saddr), "l"(g));
}
__device__ __forceinline__ void cp_commit() {
    asm volatile("cp.async.commit_group;" ::: "memory");
}
template <int N>
__device__ __forceinline__ void cp_wait() {
    asm volatile("cp.async.wait_group %0;" :: "n"(N) : "memory");
}
__device__ __forceinline__ void ldsm4(uint32_t* r, uint32_t a) {
    asm volatile("ldmatrix.sync.aligned.m8n8.x4.shared.b16 {%0,%1,%2,%3}, [%4];"
                 : "=r"(r[0]), "=r"(r[1]), "=r"(r[2]), "=r"(r[3]) : "r"(a));
}
__device__ __forceinline__ void mma_fp16(float* c, const uint32_t* a, const uint32_t* b) {
    asm volatile(
        "mma.sync.aligned.m16n8k16.row.col.f32.f16.f16.f32 "
        "{%0,%1,%2,%3}, {%4,%5,%6,%7}, {%8,%9}, {%0,%1,%2,%3};"
        : "+f"(c[0]), "+f"(c[1]), "+f"(c[2]), "+f"(c[3])
        : "r"(a[0]), "r"(a[1]), "r"(a[2]), "r"(a[3]), "r"(b[0]), "r"(b[1]));
}

// ---------------- conversions ----------------
__global__ void conv_f16(const float* __restrict__ src, __half* __restrict__ dst, int n4) {
    int i = blockIdx.x * blockDim.x + threadIdx.x;
    if (i >= n4) return;
    float4 v = ((const float4*)src)[i];
    ((__half2*)dst)[2 * i] = __floats2half2_rn(v.x, v.y);
    ((__half2*)dst)[2 * i + 1] = __floats2half2_rn(v.z, v.w);
}

__global__ void conv_w_f16(const float* __restrict__ W0, const float* __restrict__ W1,
                           const float* __restrict__ W2, const float* __restrict__ W3,
                           __half* __restrict__ dst) {
    int m = blockIdx.y;
    const float* src = (m == 0) ? W0 : (m == 1) ? W1 : (m == 2) ? W2 : W3;
    int i = blockIdx.x * blockDim.x + threadIdx.x;
    float4 v = ((const float4*)src)[i];
    size_t base = (size_t)m * (DIM * DIM / 2);
    ((__half2*)dst)[base + 2 * i] = __floats2half2_rn(v.x, v.y);
    ((__half2*)dst)[base + 2 * i + 1] = __floats2half2_rn(v.z, v.w);
}

// ---------------- fp16 HMMA GEMM, 3-stage pipeline, fused RoPE ----------------
#define BK 32
#define NCH (DIM / BK)
#define RB16 80
#define T16 (128 * RB16)     // 10240 bytes per operand tile
#define STG16 (2 * T16)      // 20480 bytes per stage
#define GS16 (3 * STG16)     // 61440

__global__ __launch_bounds__(256) void gemm_f16(
    const __half* __restrict__ Af, const __half* __restrict__ Bf,
    float* __restrict__ C0, float* __restrict__ C1, float* __restrict__ C2,
    int doRope) {
    extern __shared__ __align__(128) char smem[];
    const int tid = threadIdx.x;
    const int wid = tid >> 5, lane = tid & 31;
    const int row0 = blockIdx.y * 128, col0 = blockIdx.x * 128;
    const int wm = (wid & 1) * 64, wn = (wid >> 1) * 32;
    const uint32_t sb = s2u(smem);
    const int lr = tid >> 2, lsg = tid & 3;

#define LOAD16(c, s)                                                               \
    {                                                                              \
        uint32_t st_ = sb + (s) * STG16;                                           \
        _Pragma("unroll") for (int m_ = 0; m_ < 2; m_++) {                         \
            const __half* src_ = m_ ? Bf : Af;                                     \
            int rbase_ = m_ ? col0 : row0;                                         \
            const char* g_ = (const char*)(src_ +                                  \
                (size_t)(rbase_ + lr) * DIM + (c) * BK + lsg * 8);                 \
            uint32_t sa_ = st_ + m_ * T16 + lr * RB16 + lsg * 16;                  \
            cp16(sa_, g_);                                                         \
            cp16(sa_ + 64 * RB16, g_ + (size_t)64 * DIM * 2);                      \
        }                                                                          \
    }

    float acc[4][4][4];
#pragma unroll
    for (int i = 0; i < 4; i++)
#pragma unroll
        for (int j = 0; j < 4; j++)
#pragma unroll
            for (int u = 0; u < 4; u++) acc[i][j][u] = 0.f;

    LOAD16(0, 0); cp_commit();
    LOAD16(1, 1); cp_commit();

    const int ar = lane & 15, ac = lane >> 4;
    const int br = lane & 7, bks = (lane >> 3) & 1, bjj = (lane >> 4) & 1;

    int slot = 0;
    for (int c = 0; c < NCH; c++) {
        if (c < NCH - 1) cp_wait<1>(); else cp_wait<0>();
        __syncthreads();
        if (c + 2 < NCH) {
            int ns = slot + 2; if (ns >= 3) ns -= 3;
            LOAD16(c + 2, ns);
            cp_commit();
        }

        uint32_t st = sb + slot * STG16;
#pragma unroll
        for (int ks = 0; ks < 2; ks++) {
            uint32_t a[4][4];
#pragma unroll
            for (int i = 0; i < 4; i++) {
                uint32_t ad = st + (uint32_t)((wm + i * 16 + ar) * RB16 + (ks * 2 + ac) * 16);
                ldsm4(a[i], ad);
            }
            uint32_t b[2][4];
#pragma unroll
            for (int j2 = 0; j2 < 2; j2++) {
                uint32_t bd = st + T16 +
                              (uint32_t)((wn + j2 * 16 + bjj * 8 + br) * RB16 + (ks * 2 + bks) * 16);
                ldsm4(b[j2], bd);
            }
#pragma unroll
            for (int i = 0; i < 4; i++)
#pragma unroll
                for (int j = 0; j < 4; j++)
                    mma_fp16(acc[i][j], a[i], &b[j >> 1][(j & 1) * 2]);
        }
        slot++; if (slot == 3) slot = 0;
    }

    // epilogue: route by matrix, optional rope, fp32 float2 stores
    const int mat = col0 >> 10;
    float* Cm = (mat == 0) ? C0 : ((mat == 1) ? C1 : C2);
    const bool rope = (doRope != 0) && (mat < 2);
    const int colbase = (col0 & 1023) + wn;
#pragma unroll
    for (int j = 0; j < 4; j++) {
        int colm = colbase + j * 8 + (lane & 3) * 2;
        float invf = 0.f;
        if (rope) {
            int ip = (colm & 63) >> 1;
            invf = powf(10000.0f, -(float)ip * (1.0f / 32.0f));
        }
#pragma unroll
        for (int i = 0; i < 4; i++) {
            int row = row0 + wm + i * 16 + (lane >> 2);
            float2 v0 = {acc[i][j][0], acc[i][j][1]};
            float2 v1 = {acc[i][j][2], acc[i][j][3]};
            if (rope) {
                float s, cc;
                sincosf((float)row * invf, &s, &cc);
                v0 = {v0.x * cc - v0.y * s, v0.x * s + v0.y * cc};
                sincosf((float)(row + 8) * invf, &s, &cc);
                v1 = {v1.x * cc - v1.y * s, v1.x * s + v1.y * cc};
            }
            *(float2*)(Cm + (size_t)row * DIM + colm) = v0;
            *(float2*)(Cm + (size_t)(row + 8) * DIM + colm) = v1;
        }
    }
#undef LOAD16
}

// ---------------- tiled attention: atomic-free folded scatter ----------------
#define KVS 68
#define SK 0
#define SV (128 * KVS)                  // 8704
#define SQ (SV + 128 * KVS)             // 17408
#define SWL (SQ + 64 * 64)              // 21504  (8 warps x 8 it x 40 diagonal slots)
#define SWG (SWL + 8 * 8 * 40)          // 24064  (8 warps x 8 it x 32 global slots)
#define ATT_FLOATS (SWG + 8 * 8 * 32)   // 26112
#define ATT_SMEM (ATT_FLOATS * 4)       // 104448 bytes

__global__ __launch_bounds__(256) void attn_kernel(const float* __restrict__ Q,
                                                   const float* __restrict__ K,
                                                   const float* __restrict__ V,
                                                   __half* __restrict__ CF,
                                                   float* __restrict__ full) {
    extern __shared__ float sm[];
    const int tid = threadIdx.x;
    const int wid = tid >> 5, lane = tid & 31;
    const int t0 = blockIdx.x * 64;
    const int h = blockIdx.y;

    // load K/V rows: 0..95 = window [t0-16, t0+79], 96..127 = globals
#pragma unroll
    for (int pass = 0; pass < 8; pass++) {
        int task = tid + pass * 256;
        int r = task >> 4;
        int c4 = task & 15;
        int p = (r < 96) ? (t0 - WIN + r) : ((r - 96) * 64);
        float4 kv = {0.f, 0.f, 0.f, 0.f}, vv = {0.f, 0.f, 0.f, 0.f};
        if (p >= 0 && p < TT) {
            kv = *(const float4*)(K + (size_t)p * DIM + h * HD + c4 * 4);
            vv = *(const float4*)(V + (size_t)p * DIM + h * HD + c4 * 4);
        }
        *(float4*)&sm[SK + r * KVS + c4 * 4] = kv;
        *(float4*)&sm[SV + r * KVS + c4 * 4] = vv;
    }
    // load Q rows
#pragma unroll
    for (int pass = 0; pass < 4; pass++) {
        int task = tid + pass * 256;
        int tt = task >> 4;
        int c4 = task & 15;
        *(float4*)&sm[SQ + tt * 64 + c4 * 4] =
            *(const float4*)(Q + (size_t)(t0 + tt) * DIM + h * HD + c4 * 4);
    }
    __syncthreads();

    // phase 1: scores + softmax + atomic-free folded scatter
    for (int it = 0; it < 8; it++) {
        const int trel = wid * 8 + it;
        const int t = t0 + trel;

        int rowi[3];
        bool have[3];
        float sc[3] = {0.f, 0.f, 0.f};
#pragma unroll
        for (int u = 0; u < 3; u++) {
            int kk = u * 32 + lane;
            have[u] = (kk < NKEY);
            int r = (kk < KS) ? (trel + kk) : (96 + kk - KS);
            rowi[u] = have[u] ? r : 0;
        }
#pragma unroll
        for (int j = 0; j < 16; j++) {
            float4 q4 = *(float4*)&sm[SQ + trel * 64 + j * 4];
#pragma unroll
            for (int u = 0; u < 3; u++) {
                float4 kv = *(float4*)&sm[SK + rowi[u] * KVS + j * 4];
                sc[u] += kv.x * q4.x + kv.y * q4.y + kv.z * q4.z + kv.w * q4.w;
            }
        }
        float s0 = have[0] ? sc[0] * 0.125f : -1e30f;
        float s1 = have[1] ? sc[1] * 0.125f : -1e30f;
        float s2 = have[2] ? sc[2] * 0.125f : -1e30f;

        float m = fmaxf(fmaxf(s0, s1), s2);
#pragma unroll
        for (int o = 16; o > 0; o >>= 1) m = fmaxf(m, __shfl_xor_sync(0xFFFFFFFFu, m, o));
        float e0 = expf(s0 - m), e1 = expf(s1 - m), e2 = expf(s2 - m);
        float sum = e0 + e1 + e2;
#pragma unroll
        for (int o = 16; o > 0; o >>= 1) sum += __shfl_xor_sync(0xFFFFFFFFu, sum, o);
        const float inv = 1.f / sum;

        // weights to smem: diagonal local layout (for ctx) + global array
        float* swl = &sm[SWL + wid * 320 + it * 40];
        float* swg = &sm[SWG + wid * 256 + it * 32];
        if (lane < 40) swl[lane] = 0.f;
        if (lane < 8) swl[lane + 32] = 0.f;
        __syncwarp();
        float ee[3] = {e0, e1, e2};
#pragma unroll
        for (int u = 0; u < 3; u++) {
            int kk = u * 32 + lane;
            if (kk < NKEY) {
                float w = ee[u] * inv;
                if (kk < KS) swl[it + kk] = w;
                else swg[kk - KS] = w;
            }
        }
        __syncwarp();

        // scatter: warp owns row (h,t); fold global into overlapping local col
        const int left = max(t - WIN, 0);
        const int right = min(t + WIN + 1, TT);
        float* rowp = full + ((size_t)h * TT + t) * TT;
#pragma unroll
        for (int u = 0; u < 2; u++) {
            int kk = u * 32 + lane;
            if (kk < KS) {
                int col = left + kk;
                if (col < right) {
                    float w = swl[it + kk];
                    if ((col & 63) == 0) w += swg[col >> 6];
                    rowp[col] = w;
                }
            }
        }
        {
            int col = lane * 64;  // global col
            if (!(col >= left && col < right)) rowp[col] = swg[lane];
        }
    }

    // phase 2: ctx register tile (8 t's per warp, stream V rows once)
    float a0[8], a1[8];
#pragma unroll
    for (int it = 0; it < 8; it++) { a0[it] = 0.f; a1[it] = 0.f; }

    const float* swlb = &sm[SWL + wid * 320];
    const float* swgb = &sm[SWG + wid * 256];
#pragma unroll 4
    for (int j = 0; j < 40; j++) {
        int r = wid * 8 + j;
        float2 v2 = *(float2*)&sm[SV + r * KVS + 2 * lane];
#pragma unroll
        for (int it = 0; it < 8; it++) {
            float w = swlb[it * 40 + j];
            a0[it] += w * v2.x;
            a1[it] += w * v2.y;
        }
    }
#pragma unroll 4
    for (int g = 0; g < 32; g++) {
        float2 v2 = *(float2*)&sm[SV + (96 + g) * KVS + 2 * lane];
#pragma unroll
        for (int it = 0; it < 8; it++) {
            float w = swgb[it * 32 + g];
            a0[it] += w * v2.x;
            a1[it] += w * v2.y;
        }
    }

#pragma unroll
    for (int it = 0; it < 8; it++) {
        int t = t0 + wid * 8 + it;
        size_t co = ((size_t)t * DIM + h * HD) / 2 + lane;
        ((__half2*)CF)[co] = __floats2half2_rn(a0[it], a1[it]);
    }
}

// ---------------- kernel_launch ----------------
extern "C" void kernel_launch(void* const* d_in, const int* in_sizes, int n_in,
                              void* d_out, int out_size) {
    const float* x  = (const float*)d_in[0];
    const float* Wq = (const float*)d_in[1];
    const float* Wk = (const float*)d_in[2];
    const float* Wv = (const float*)d_in[3];
    const float* Wo = (const float*)d_in[4];

    float* out  = (float*)d_out;
    float* full = (float*)d_out + (size_t)TT * DIM;

    float *Q, *Kb, *V;
    cudaGetSymbolAddress((void**)&Q,  g_Q);
    cudaGetSymbolAddress((void**)&Kb, g_K);
    cudaGetSymbolAddress((void**)&V,  g_V);
    __half *xf, *wf, *cf;
    cudaGetSymbolAddress((void**)&xf, g_xf);
    cudaGetSymbolAddress((void**)&wf, g_wf);
    cudaGetSymbolAddress((void**)&cf, g_cf);

    cudaFuncSetAttribute(gemm_f16, cudaFuncAttributeMaxDynamicSharedMemorySize, GS16);
    cudaFuncSetAttribute(attn_kernel, cudaFuncAttributeMaxDynamicSharedMemorySize, ATT_SMEM);

    // side stream + events for a parallel memset branch in the captured graph
    static cudaStream_t s2 = nullptr;
    static cudaEvent_t evFork = nullptr, evJoin = nullptr;
    if (s2 == nullptr) {
        cudaStreamCreateWithFlags(&s2, cudaStreamNonBlocking);
        cudaEventCreateWithFlags(&evFork, cudaEventDisableTiming);
        cudaEventCreateWithFlags(&evJoin, cudaEventDisableTiming);
    }

    // fork: zero `full` (268MB) concurrently with conversions + QKV GEMM
    cudaEventRecord(evFork, 0);
    cudaStreamWaitEvent(s2, evFork, 0);
    cudaMemsetAsync(full, 0, (size_t)NH * TT * TT * sizeof(float), s2);
    cudaEventRecord(evJoin, s2);

    // conversions (main stream)
    {
        int n4x = TT * DIM / 4;
        conv_f16<<<(n4x + 255) / 256, 256>>>(x, xf, n4x);
        dim3 gw(DIM * DIM / 4 / 256, 4);
        conv_w_f16<<<gw, 256>>>(Wq, Wk, Wv, Wo, wf);
    }

    // fused QKV projection + RoPE (fp16 single product)
    {
        dim3 gg(3 * DIM / 128, TT / 128);  // (24, 16)
        gemm_f16<<<gg, 256, GS16>>>(xf, wf, Q, Kb, V, 1);
    }

    // join: attn writes into `full`
    cudaStreamWaitEvent(0, evJoin, 0);

    // tiled attention (folded scatter, writes ctx fp16)
    {
        dim3 ga(TT / 64, NH);  // (32, 16)
        attn_kernel<<<ga, 256, ATT_SMEM>>>(Q, Kb, V, cf, full);
    }

    // output projection (fp16 single product)
    {
        dim3 gg(DIM / 128, TT / 128);  // (8, 16)
        gemm_f16<<<gg, 256, GS16>>>(cf, wf + 3 * (size_t)DIM * DIM, out, out, out, 0);
    }
}

// round 14
// speedup vs baseline: 1.0299x; 1.0299x over previous
#include <cuda_runtime.h>
#include <cuda_bf16.h>
#include <cuda_fp16.h>
#include <math.h>
#include <cstdint>

#define TT 2048
#define DIM 1024
#define NH 16
#define HD 64
#define WIN 16
#define KS 33
#define NG 32
#define NKEY (KS + NG)

// ---------------- scratch (device globals, no allocation) ----------------
__device__ float g_Q[TT * DIM];
__device__ float g_K[TT * DIM];
__device__ float g_V[TT * DIM];
__device__ __half g_xf[TT * DIM];
__device__ __half g_wf[4 * DIM * DIM];
__device__ __half g_cf[TT * DIM];

// ---------------- PTX helpers (sm_80-generic only) ----------------
__device__ __forceinline__ uint32_t s2u(const void* p) {
    uint32_t a;
    asm("{ .reg .u64 t; cvta.to.shared.u64 t, %1; cvt.u32.u64 %0, t; }" : "=r"(a) : "l"(p));
    return a;
}
__device__ __forceinline__ void cp16(uint32_t saddr, const void* g) {
    asm volatile("cp.async.cg.shared.global [%0], [%1], 16;" :: "r"(saddr), "l"(g));
}
__device__ __forceinline__ void cp_commit() {
    asm volatile("cp.async.commit_group;" ::: "memory");
}
template <int N>
__device__ __forceinline__ void cp_wait() {
    asm volatile("cp.async.wait_group %0;" :: "n"(N) : "memory");
}
__device__ __forceinline__ void ldsm4(uint32_t* r, uint32_t a) {
    asm volatile("ldmatrix.sync.aligned.m8n8.x4.shared.b16 {%0,%1,%2,%3}, [%4];"
                 : "=r"(r[0]), "=r"(r[1]), "=r"(r[2]), "=r"(r[3]) : "r"(a));
}
__device__ __forceinline__ void mma_fp16(float* c, const uint32_t* a, const uint32_t* b) {
    asm volatile(
        "mma.sync.aligned.m16n8k16.row.col.f32.f16.f16.f32 "
        "{%0,%1,%2,%3}, {%4,%5,%6,%7}, {%8,%9}, {%0,%1,%2,%3};"
        : "+f"(c[0]), "+f"(c[1]), "+f"(c[2]), "+f"(c[3])
        : "r"(a[0]), "r"(a[1]), "r"(a[2]), "r"(a[3]), "r"(b[0]), "r"(b[1]));
}

// ---------------- conversions ----------------
__global__ void conv_f16(const float* __restrict__ src, __half* __restrict__ dst, int n4) {
    int i = blockIdx.x * blockDim.x + threadIdx.x;
    if (i >= n4) return;
    float4 v = ((const float4*)src)[i];
    ((__half2*)dst)[2 * i] = __floats2half2_rn(v.x, v.y);
    ((__half2*)dst)[2 * i + 1] = __floats2half2_rn(v.z, v.w);
}

__global__ void conv_w_f16(const float* __restrict__ W0, const float* __restrict__ W1,
                           const float* __restrict__ W2, const float* __restrict__ W3,
                           __half* __restrict__ dst) {
    int m = blockIdx.y;
    const float* src = (m == 0) ? W0 : (m == 1) ? W1 : (m == 2) ? W2 : W3;
    int i = blockIdx.x * blockDim.x + threadIdx.x;
    float4 v = ((const float4*)src)[i];
    size_t base = (size_t)m * (DIM * DIM / 2);
    ((__half2*)dst)[base + 2 * i] = __floats2half2_rn(v.x, v.y);
    ((__half2*)dst)[base + 2 * i + 1] = __floats2half2_rn(v.z, v.w);
}

// ---------------- fp16 HMMA GEMM, 3-stage pipeline, fused RoPE ----------------
#define BK 32
#define NCH (DIM / BK)
#define RB16 80
#define T16 (128 * RB16)     // 10240 bytes per operand tile
#define STG16 (2 * T16)      // 20480 bytes per stage
#define GS16 (3 * STG16)     // 61440

__global__ __launch_bounds__(256) void gemm_f16(
    const __half* __restrict__ Af, const __half* __restrict__ Bf,
    float* __restrict__ C0, float* __restrict__ C1, float* __restrict__ C2,
    int doRope) {
    extern __shared__ __align__(128) char smem[];
    const int tid = threadIdx.x;
    const int wid = tid >> 5, lane = tid & 31;
    const int row0 = blockIdx.y * 128, col0 = blockIdx.x * 128;
    const int wm = (wid & 1) * 64, wn = (wid >> 1) * 32;
    const uint32_t sb = s2u(smem);
    const int lr = tid >> 2, lsg = tid & 3;

#define LOAD16(c, s)                                                               \
    {                                                                              \
        uint32_t st_ = sb + (s) * STG16;                                           \
        _Pragma("unroll") for (int m_ = 0; m_ < 2; m_++) {                         \
            const __half* src_ = m_ ? Bf : Af;                                     \
            int rbase_ = m_ ? col0 : row0;                                         \
            const char* g_ = (const char*)(src_ +                                  \
                (size_t)(rbase_ + lr) * DIM + (c) * BK + lsg * 8);                 \
            uint32_t sa_ = st_ + m_ * T16 + lr * RB16 + lsg * 16;                  \
            cp16(sa_, g_);                                                         \
            cp16(sa_ + 64 * RB16, g_ + (size_t)64 * DIM * 2);                      \
        }                                                                          \
    }

    float acc[4][4][4];
#pragma unroll
    for (int i = 0; i < 4; i++)
#pragma unroll
        for (int j = 0; j < 4; j++)
#pragma unroll
            for (int u = 0; u < 4; u++) acc[i][j][u] = 0.f;

    LOAD16(0, 0); cp_commit();
    LOAD16(1, 1); cp_commit();

    const int ar = lane & 15, ac = lane >> 4;
    const int br = lane & 7, bks = (lane >> 3) & 1, bjj = (lane >> 4) & 1;

    int slot = 0;
    for (int c = 0; c < NCH; c++) {
        if (c < NCH - 1) cp_wait<1>(); else cp_wait<0>();
        __syncthreads();
        if (c + 2 < NCH) {
            int ns = slot + 2; if (ns >= 3) ns -= 3;
            LOAD16(c + 2, ns);
            cp_commit();
        }

        uint32_t st = sb + slot * STG16;
#pragma unroll
        for (int ks = 0; ks < 2; ks++) {
            uint32_t a[4][4];
#pragma unroll
            for (int i = 0; i < 4; i++) {
                uint32_t ad = st + (uint32_t)((wm + i * 16 + ar) * RB16 + (ks * 2 + ac) * 16);
                ldsm4(a[i], ad);
            }
            uint32_t b[2][4];
#pragma unroll
            for (int j2 = 0; j2 < 2; j2++) {
                uint32_t bd = st + T16 +
                              (uint32_t)((wn + j2 * 16 + bjj * 8 + br) * RB16 + (ks * 2 + bks) * 16);
                ldsm4(b[j2], bd);
            }
#pragma unroll
            for (int i = 0; i < 4; i++)
#pragma unroll
                for (int j = 0; j < 4; j++)
                    mma_fp16(acc[i][j], a[i], &b[j >> 1][(j & 1) * 2]);
        }
        slot++; if (slot == 3) slot = 0;
    }

    // epilogue: route by matrix, optional rope, fp32 float2 stores
    const int mat = col0 >> 10;
    float* Cm = (mat == 0) ? C0 : ((mat == 1) ? C1 : C2);
    const bool rope = (doRope != 0) && (mat < 2);
    const int colbase = (col0 & 1023) + wn;
#pragma unroll
    for (int j = 0; j < 4; j++) {
        int colm = colbase + j * 8 + (lane & 3) * 2;
        float invf = 0.f;
        if (rope) {
            int ip = (colm & 63) >> 1;
            invf = powf(10000.0f, -(float)ip * (1.0f / 32.0f));
        }
#pragma unroll
        for (int i = 0; i < 4; i++) {
            int row = row0 + wm + i * 16 + (lane >> 2);
            float2 v0 = {acc[i][j][0], acc[i][j][1]};
            float2 v1 = {acc[i][j][2], acc[i][j][3]};
            if (rope) {
                float s, cc;
                sincosf((float)row * invf, &s, &cc);
                v0 = {v0.x * cc - v0.y * s, v0.x * s + v0.y * cc};
                sincosf((float)(row + 8) * invf, &s, &cc);
                v1 = {v1.x * cc - v1.y * s, v1.x * s + v1.y * cc};
            }
            *(float2*)(Cm + (size_t)row * DIM + colm) = v0;
            *(float2*)(Cm + (size_t)(row + 8) * DIM + colm) = v1;
        }
    }
#undef LOAD16
}

// ---------------- tiled attention: fused zeroing + atomic-free folded scatter ----------------
#define KVS 68
#define SK 0
#define SV (128 * KVS)                  // 8704
#define SQ (SV + 128 * KVS)             // 17408
#define SWL (SQ + 64 * 64)              // 21504  (8 warps x 8 it x 40 diagonal slots)
#define SWG (SWL + 8 * 8 * 40)          // 24064  (8 warps x 8 it x 32 global slots)
#define ATT_FLOATS (SWG + 8 * 8 * 32)   // 26112
#define ATT_SMEM (ATT_FLOATS * 4)       // 104448 bytes

__global__ __launch_bounds__(256) void attn_kernel(const float* __restrict__ Q,
                                                   const float* __restrict__ K,
                                                   const float* __restrict__ V,
                                                   __half* __restrict__ CF,
                                                   float* __restrict__ full) {
    extern __shared__ float sm[];
    const int tid = threadIdx.x;
    const int wid = tid >> 5, lane = tid & 31;
    const int t0 = blockIdx.x * 64;
    const int h = blockIdx.y;

    // load K/V rows: 0..95 = window [t0-16, t0+79], 96..127 = globals
#pragma unroll
    for (int pass = 0; pass < 8; pass++) {
        int task = tid + pass * 256;
        int r = task >> 4;
        int c4 = task & 15;
        int p = (r < 96) ? (t0 - WIN + r) : ((r - 96) * 64);
        float4 kv = {0.f, 0.f, 0.f, 0.f}, vv = {0.f, 0.f, 0.f, 0.f};
        if (p >= 0 && p < TT) {
            kv = *(const float4*)(K + (size_t)p * DIM + h * HD + c4 * 4);
            vv = *(const float4*)(V + (size_t)p * DIM + h * HD + c4 * 4);
        }
        *(float4*)&sm[SK + r * KVS + c4 * 4] = kv;
        *(float4*)&sm[SV + r * KVS + c4 * 4] = vv;
    }
    // load Q rows
#pragma unroll
    for (int pass = 0; pass < 4; pass++) {
        int task = tid + pass * 256;
        int tt = task >> 4;
        int c4 = task & 15;
        *(float4*)&sm[SQ + tt * 64 + c4 * 4] =
            *(const float4*)(Q + (size_t)(t0 + tt) * DIM + h * HD + c4 * 4);
    }

    // zero this warp's 8 rows of `full` (streaming stores; overlaps smem fill)
    {
        float* rowbase = full + ((size_t)h * TT + t0 + wid * 8) * TT;
        float4 z4 = {0.f, 0.f, 0.f, 0.f};
#pragma unroll
        for (int it = 0; it < 8; it++) {
            float* rowp = rowbase + (size_t)it * TT;
#pragma unroll
            for (int z = 0; z < 16; z++)
                __stcs((float4*)(rowp + (z * 32 + lane) * 4), z4);
        }
    }
    __syncthreads();

    // phase 1: scores + softmax + atomic-free folded scatter
    for (int it = 0; it < 8; it++) {
        const int trel = wid * 8 + it;
        const int t = t0 + trel;

        int rowi[3];
        bool have[3];
        float sc[3] = {0.f, 0.f, 0.f};
#pragma unroll
        for (int u = 0; u < 3; u++) {
            int kk = u * 32 + lane;
            have[u] = (kk < NKEY);
            int r = (kk < KS) ? (trel + kk) : (96 + kk - KS);
            rowi[u] = have[u] ? r : 0;
        }
#pragma unroll
        for (int j = 0; j < 16; j++) {
            float4 q4 = *(float4*)&sm[SQ + trel * 64 + j * 4];
#pragma unroll
            for (int u = 0; u < 3; u++) {
                float4 kv = *(float4*)&sm[SK + rowi[u] * KVS + j * 4];
                sc[u] += kv.x * q4.x + kv.y * q4.y + kv.z * q4.z + kv.w * q4.w;
            }
        }
        float s0 = have[0] ? sc[0] * 0.125f : -1e30f;
        float s1 = have[1] ? sc[1] * 0.125f : -1e30f;
        float s2 = have[2] ? sc[2] * 0.125f : -1e30f;

        float m = fmaxf(fmaxf(s0, s1), s2);
#pragma unroll
        for (int o = 16; o > 0; o >>= 1) m = fmaxf(m, __shfl_xor_sync(0xFFFFFFFFu, m, o));
        float e0 = expf(s0 - m), e1 = expf(s1 - m), e2 = expf(s2 - m);
        float sum = e0 + e1 + e2;
#pragma unroll
        for (int o = 16; o > 0; o >>= 1) sum += __shfl_xor_sync(0xFFFFFFFFu, sum, o);
        const float inv = 1.f / sum;

        // weights to smem: diagonal local layout (for ctx) + global array
        float* swl = &sm[SWL + wid * 320 + it * 40];
        float* swg = &sm[SWG + wid * 256 + it * 32];
        if (lane < 40) swl[lane] = 0.f;
        if (lane < 8) swl[lane + 32] = 0.f;
        __syncwarp();
        float ee[3] = {e0, e1, e2};
#pragma unroll
        for (int u = 0; u < 3; u++) {
            int kk = u * 32 + lane;
            if (kk < NKEY) {
                float w = ee[u] * inv;
                if (kk < KS) swl[it + kk] = w;
                else swg[kk - KS] = w;
            }
        }
        __syncwarp();

        // scatter: warp owns row (h,t); fold global into overlapping local col
        const int left = max(t - WIN, 0);
        const int right = min(t + WIN + 1, TT);
        float* rowp = full + ((size_t)h * TT + t) * TT;
#pragma unroll
        for (int u = 0; u < 2; u++) {
            int kk = u * 32 + lane;
            if (kk < KS) {
                int col = left + kk;
                if (col < right) {
                    float w = swl[it + kk];
                    if ((col & 63) == 0) w += swg[col >> 6];
                    rowp[col] = w;
                }
            }
        }
        {
            int col = lane * 64;  // global col
            if (!(col >= left && col < right)) rowp[col] = swg[lane];
        }
    }

    // phase 2: ctx register tile (8 t's per warp, stream V rows once)
    float a0[8], a1[8];
#pragma unroll
    for (int it = 0; it < 8; it++) { a0[it] = 0.f; a1[it] = 0.f; }

    const float* swlb = &sm[SWL + wid * 320];
    const float* swgb = &sm[SWG + wid * 256];
#pragma unroll 4
    for (int j = 0; j < 40; j++) {
        int r = wid * 8 + j;
        float2 v2 = *(float2*)&sm[SV + r * KVS + 2 * lane];
#pragma unroll
        for (int it = 0; it < 8; it++) {
            float w = swlb[it * 40 + j];
            a0[it] += w * v2.x;
            a1[it] += w * v2.y;
        }
    }
#pragma unroll 4
    for (int g = 0; g < 32; g++) {
        float2 v2 = *(float2*)&sm[SV + (96 + g) * KVS + 2 * lane];
#pragma unroll
        for (int it = 0; it < 8; it++) {
            float w = swgb[it * 32 + g];
            a0[it] += w * v2.x;
            a1[it] += w * v2.y;
        }
    }

#pragma unroll
    for (int it = 0; it < 8; it++) {
        int t = t0 + wid * 8 + it;
        size_t co = ((size_t)t * DIM + h * HD) / 2 + lane;
        ((__half2*)CF)[co] = __floats2half2_rn(a0[it], a1[it]);
    }
}

// ---------------- kernel_launch ----------------
extern "C" void kernel_launch(void* const* d_in, const int* in_sizes, int n_in,
                              void* d_out, int out_size) {
    const float* x  = (const float*)d_in[0];
    const float* Wq = (const float*)d_in[1];
    const float* Wk = (const float*)d_in[2];
    const float* Wv = (const float*)d_in[3];
    const float* Wo = (const float*)d_in[4];

    float* out  = (float*)d_out;
    float* full = (float*)d_out + (size_t)TT * DIM;

    float *Q, *Kb, *V;
    cudaGetSymbolAddress((void**)&Q,  g_Q);
    cudaGetSymbolAddress((void**)&Kb, g_K);
    cudaGetSymbolAddress((void**)&V,  g_V);
    __half *xf, *wf, *cf;
    cudaGetSymbolAddress((void**)&xf, g_xf);
    cudaGetSymbolAddress((void**)&wf, g_wf);
    cudaGetSymbolAddress((void**)&cf, g_cf);

    cudaFuncSetAttribute(gemm_f16, cudaFuncAttributeMaxDynamicSharedMemorySize, GS16);
    cudaFuncSetAttribute(attn_kernel, cudaFuncAttributeMaxDynamicSharedMemorySize, ATT_SMEM);

    // conversions
    {
        int n4x = TT * DIM / 4;
        conv_f16<<<(n4x + 255) / 256, 256>>>(x, xf, n4x);
        dim3 gw(DIM * DIM / 4 / 256, 4);
        conv_w_f16<<<gw, 256>>>(Wq, Wk, Wv, Wo, wf);
    }

    // fused QKV projection + RoPE (fp16 single product)
    {
        dim3 gg(3 * DIM / 128, TT / 128);  // (24, 16)
        gemm_f16<<<gg, 256, GS16>>>(xf, wf, Q, Kb, V, 1);
    }

    // tiled attention (zeroes + scatters `full`, writes ctx fp16)
    {
        dim3 ga(TT / 64, NH);  // (32, 16)
        attn_kernel<<<ga, 256, ATT_SMEM>>>(Q, Kb, V, cf, full);
    }

    // output projection (fp16 single product)
    {
        dim3 gg(DIM / 128, TT / 128);  // (8, 16)
        gemm_f16<<<gg, 256, GS16>>>(cf, wf + 3 * (size_t)DIM * DIM, out, out, out, 0);
    }
}

// round 15
// speedup vs baseline: 1.1268x; 1.0941x over previous
#include <cuda_runtime.h>
#include <cuda_bf16.h>
#include <cuda_fp16.h>
#include <math.h>
#include <cstdint>

#define TT 2048
#define DIM 1024
#define NH 16
#define HD 64
#define WIN 16
#define KS 33
#define NG 32
#define NKEY (KS + NG)

// ---------------- scratch (device globals, no allocation) ----------------
__device__ float g_Q[TT * DIM];
__device__ float g_K[TT * DIM];
__device__ float g_V[TT * DIM];
__device__ __half g_xf[TT * DIM];
__device__ __half g_wf[4 * DIM * DIM];
__device__ __half g_cf[TT * DIM];

// ---------------- PTX helpers (sm_80-generic only) ----------------
__device__ __forceinline__ uint32_t s2u(const void* p) {
    uint32_t a;
    asm("{ .reg .u64 t; cvta.to.shared.u64 t, %1; cvt.u32.u64 %0, t; }" : "=r"(a) : "l"(p));
    return a;
}
__device__ __forceinline__ void cp16(uint32_t saddr, const void* g) {
    asm volatile("cp.async.cg.shared.global [%0], [%1], 16;" :: "r"(saddr), "l"(g));
}
__device__ __forceinline__ void cp_commit() {
    asm volatile("cp.async.commit_group;" ::: "memory");
}
template <int N>
__device__ __forceinline__ void cp_wait() {
    asm volatile("cp.async.wait_group %0;" :: "n"(N) : "memory");
}
__device__ __forceinline__ void ldsm4(uint32_t* r, uint32_t a) {
    asm volatile("ldmatrix.sync.aligned.m8n8.x4.shared.b16 {%0,%1,%2,%3}, [%4];"
                 : "=r"(r[0]), "=r"(r[1]), "=r"(r[2]), "=r"(r[3]) : "r"(a));
}
__device__ __forceinline__ void mma_fp16(float* c, const uint32_t* a, const uint32_t* b) {
    asm volatile(
        "mma.sync.aligned.m16n8k16.row.col.f32.f16.f16.f32 "
        "{%0,%1,%2,%3}, {%4,%5,%6,%7}, {%8,%9}, {%0,%1,%2,%3};"
        : "+f"(c[0]), "+f"(c[1]), "+f"(c[2]), "+f"(c[3])
        : "r"(a[0]), "r"(a[1]), "r"(a[2]), "r"(a[3]), "r"(b[0]), "r"(b[1]));
}

// ---------------- conversions ----------------
__global__ void conv_f16(const float* __restrict__ src, __half* __restrict__ dst, int n4) {
    int i = blockIdx.x * blockDim.x + threadIdx.x;
    if (i >= n4) return;
    float4 v = ((const float4*)src)[i];
    ((__half2*)dst)[2 * i] = __floats2half2_rn(v.x, v.y);
    ((__half2*)dst)[2 * i + 1] = __floats2half2_rn(v.z, v.w);
}

__global__ void conv_w_f16(const float* __restrict__ W0, const float* __restrict__ W1,
                           const float* __restrict__ W2, const float* __restrict__ W3,
                           __half* __restrict__ dst) {
    int m = blockIdx.y;
    const float* src = (m == 0) ? W0 : (m == 1) ? W1 : (m == 2) ? W2 : W3;
    int i = blockIdx.x * blockDim.x + threadIdx.x;
    float4 v = ((const float4*)src)[i];
    size_t base = (size_t)m * (DIM * DIM / 2);
    ((__half2*)dst)[base + 2 * i] = __floats2half2_rn(v.x, v.y);
    ((__half2*)dst)[base + 2 * i + 1] = __floats2half2_rn(v.z, v.w);
}

// ---------------- fp16 HMMA GEMM, 3-stage pipeline, fused RoPE ----------------
#define BK 32
#define NCH (DIM / BK)
#define RB16 80
#define T16 (128 * RB16)     // 10240 bytes per operand tile
#define STG16 (2 * T16)      // 20480 bytes per stage
#define GS16 (3 * STG16)     // 61440

__global__ __launch_bounds__(256) void gemm_f16(
    const __half* __restrict__ Af, const __half* __restrict__ Bf,
    float* __restrict__ C0, float* __restrict__ C1, float* __restrict__ C2,
    int doRope) {
    extern __shared__ __align__(128) char smem[];
    const int tid = threadIdx.x;
    const int wid = tid >> 5, lane = tid & 31;
    const int row0 = blockIdx.y * 128, col0 = blockIdx.x * 128;
    const int wm = (wid & 1) * 64, wn = (wid >> 1) * 32;
    const uint32_t sb = s2u(smem);
    const int lr = tid >> 2, lsg = tid & 3;

#define LOAD16(c, s)                                                               \
    {                                                                              \
        uint32_t st_ = sb + (s) * STG16;                                           \
        _Pragma("unroll") for (int m_ = 0; m_ < 2; m_++) {                         \
            const __half* src_ = m_ ? Bf : Af;                                     \
            int rbase_ = m_ ? col0 : row0;                                         \
            const char* g_ = (const char*)(src_ +                                  \
                (size_t)(rbase_ + lr) * DIM + (c) * BK + lsg * 8);                 \
            uint32_t sa_ = st_ + m_ * T16 + lr * RB16 + lsg * 16;                  \
            cp16(sa_, g_);                                                         \
            cp16(sa_ + 64 * RB16, g_ + (size_t)64 * DIM * 2);                      \
        }                                                                          \
    }

    float acc[4][4][4];
#pragma unroll
    for (int i = 0; i < 4; i++)
#pragma unroll
        for (int j = 0; j < 4; j++)
#pragma unroll
            for (int u = 0; u < 4; u++) acc[i][j][u] = 0.f;

    LOAD16(0, 0); cp_commit();
    LOAD16(1, 1); cp_commit();

    const int ar = lane & 15, ac = lane >> 4;
    const int br = lane & 7, bks = (lane >> 3) & 1, bjj = (lane >> 4) & 1;

    int slot = 0;
    for (int c = 0; c < NCH; c++) {
        if (c < NCH - 1) cp_wait<1>(); else cp_wait<0>();
        __syncthreads();
        if (c + 2 < NCH) {
            int ns = slot + 2; if (ns >= 3) ns -= 3;
            LOAD16(c + 2, ns);
            cp_commit();
        }

        uint32_t st = sb + slot * STG16;
#pragma unroll
        for (int ks = 0; ks < 2; ks++) {
            uint32_t a[4][4];
#pragma unroll
            for (int i = 0; i < 4; i++) {
                uint32_t ad = st + (uint32_t)((wm + i * 16 + ar) * RB16 + (ks * 2 + ac) * 16);
                ldsm4(a[i], ad);
            }
            uint32_t b[2][4];
#pragma unroll
            for (int j2 = 0; j2 < 2; j2++) {
                uint32_t bd = st + T16 +
                              (uint32_t)((wn + j2 * 16 + bjj * 8 + br) * RB16 + (ks * 2 + bks) * 16);
                ldsm4(b[j2], bd);
            }
#pragma unroll
            for (int i = 0; i < 4; i++)
#pragma unroll
                for (int j = 0; j < 4; j++)
                    mma_fp16(acc[i][j], a[i], &b[j >> 1][(j & 1) * 2]);
        }
        slot++; if (slot == 3) slot = 0;
    }

    // epilogue: route by matrix, optional rope, fp32 float2 stores
    const int mat = col0 >> 10;
    float* Cm = (mat == 0) ? C0 : ((mat == 1) ? C1 : C2);
    const bool rope = (doRope != 0) && (mat < 2);
    const int colbase = (col0 & 1023) + wn;
#pragma unroll
    for (int j = 0; j < 4; j++) {
        int colm = colbase + j * 8 + (lane & 3) * 2;
        float invf = 0.f;
        if (rope) {
            int ip = (colm & 63) >> 1;
            invf = powf(10000.0f, -(float)ip * (1.0f / 32.0f));
        }
#pragma unroll
        for (int i = 0; i < 4; i++) {
            int row = row0 + wm + i * 16 + (lane >> 2);
            float2 v0 = {acc[i][j][0], acc[i][j][1]};
            float2 v1 = {acc[i][j][2], acc[i][j][3]};
            if (rope) {
                float s, cc;
                sincosf((float)row * invf, &s, &cc);
                v0 = {v0.x * cc - v0.y * s, v0.x * s + v0.y * cc};
                sincosf((float)(row + 8) * invf, &s, &cc);
                v1 = {v1.x * cc - v1.y * s, v1.x * s + v1.y * cc};
            }
            *(float2*)(Cm + (size_t)row * DIM + colm) = v0;
            *(float2*)(Cm + (size_t)(row + 8) * DIM + colm) = v1;
        }
    }
#undef LOAD16
}

// ---------------- tiled attention: per-it zeroing + atomic-free folded scatter ----------------
#define KVS 68
#define SK 0
#define SV (128 * KVS)                  // 8704
#define SQ (SV + 128 * KVS)             // 17408
#define SWL (SQ + 64 * 64)              // 21504  (8 warps x 8 it x 40 diagonal slots)
#define SWG (SWL + 8 * 8 * 40)          // 24064  (8 warps x 8 it x 32 global slots)
#define ATT_FLOATS (SWG + 8 * 8 * 32)   // 26112
#define ATT_SMEM (ATT_FLOATS * 4)       // 104448 bytes

__global__ __launch_bounds__(256) void attn_kernel(const float* __restrict__ Q,
                                                   const float* __restrict__ K,
                                                   const float* __restrict__ V,
                                                   __half* __restrict__ CF,
                                                   float* __restrict__ full) {
    extern __shared__ float sm[];
    const int tid = threadIdx.x;
    const int wid = tid >> 5, lane = tid & 31;
    const int t0 = blockIdx.x * 64;
    const int h = blockIdx.y;

    // load K/V rows: 0..95 = window [t0-16, t0+79], 96..127 = globals
#pragma unroll
    for (int pass = 0; pass < 8; pass++) {
        int task = tid + pass * 256;
        int r = task >> 4;
        int c4 = task & 15;
        int p = (r < 96) ? (t0 - WIN + r) : ((r - 96) * 64);
        float4 kv = {0.f, 0.f, 0.f, 0.f}, vv = {0.f, 0.f, 0.f, 0.f};
        if (p >= 0 && p < TT) {
            kv = *(const float4*)(K + (size_t)p * DIM + h * HD + c4 * 4);
            vv = *(const float4*)(V + (size_t)p * DIM + h * HD + c4 * 4);
        }
        *(float4*)&sm[SK + r * KVS + c4 * 4] = kv;
        *(float4*)&sm[SV + r * KVS + c4 * 4] = vv;
    }
    // load Q rows
#pragma unroll
    for (int pass = 0; pass < 4; pass++) {
        int task = tid + pass * 256;
        int tt = task >> 4;
        int c4 = task & 15;
        *(float4*)&sm[SQ + tt * 64 + c4 * 4] =
            *(const float4*)(Q + (size_t)(t0 + tt) * DIM + h * HD + c4 * 4);
    }
    __syncthreads();

    // phase 1: per-it zero + scores + softmax + atomic-free folded scatter
    for (int it = 0; it < 8; it++) {
        const int trel = wid * 8 + it;
        const int t = t0 + trel;
        float* rowp = full + ((size_t)h * TT + t) * TT;

        // zero this row (dependency-free float4 stream; interleaves with compute below)
        float4 z4 = {0.f, 0.f, 0.f, 0.f};
#pragma unroll
        for (int z = 0; z < 16; z++) *(float4*)(rowp + (z * 32 + lane) * 4) = z4;

        int rowi[3];
        bool have[3];
        float sc[3] = {0.f, 0.f, 0.f};
#pragma unroll
        for (int u = 0; u < 3; u++) {
            int kk = u * 32 + lane;
            have[u] = (kk < NKEY);
            int r = (kk < KS) ? (trel + kk) : (96 + kk - KS);
            rowi[u] = have[u] ? r : 0;
        }
#pragma unroll
        for (int j = 0; j < 16; j++) {
            float4 q4 = *(float4*)&sm[SQ + trel * 64 + j * 4];
#pragma unroll
            for (int u = 0; u < 3; u++) {
                float4 kv = *(float4*)&sm[SK + rowi[u] * KVS + j * 4];
                sc[u] += kv.x * q4.x + kv.y * q4.y + kv.z * q4.z + kv.w * q4.w;
            }
        }
        float s0 = have[0] ? sc[0] * 0.125f : -1e30f;
        float s1 = have[1] ? sc[1] * 0.125f : -1e30f;
        float s2 = have[2] ? sc[2] * 0.125f : -1e30f;

        float m = fmaxf(fmaxf(s0, s1), s2);
#pragma unroll
        for (int o = 16; o > 0; o >>= 1) m = fmaxf(m, __shfl_xor_sync(0xFFFFFFFFu, m, o));
        float e0 = expf(s0 - m), e1 = expf(s1 - m), e2 = expf(s2 - m);
        float sum = e0 + e1 + e2;
#pragma unroll
        for (int o = 16; o > 0; o >>= 1) sum += __shfl_xor_sync(0xFFFFFFFFu, sum, o);
        const float inv = 1.f / sum;

        // weights to smem: diagonal local layout (for ctx) + global array
        float* swl = &sm[SWL + wid * 320 + it * 40];
        float* swg = &sm[SWG + wid * 256 + it * 32];
        if (lane < 40) swl[lane] = 0.f;
        if (lane < 8) swl[lane + 32] = 0.f;
        __syncwarp();
        float ee[3] = {e0, e1, e2};
#pragma unroll
        for (int u = 0; u < 3; u++) {
            int kk = u * 32 + lane;
            if (kk < NKEY) {
                float w = ee[u] * inv;
                if (kk < KS) swl[it + kk] = w;
                else swg[kk - KS] = w;
            }
        }
        __syncwarp();

        // scatter: warp owns row (h,t); fold global into overlapping local col
        const int left = max(t - WIN, 0);
        const int right = min(t + WIN + 1, TT);
#pragma unroll
        for (int u = 0; u < 2; u++) {
            int kk = u * 32 + lane;
            if (kk < KS) {
                int col = left + kk;
                if (col < right) {
                    float w = swl[it + kk];
                    if ((col & 63) == 0) w += swg[col >> 6];
                    rowp[col] = w;
                }
            }
        }
        {
            int col = lane * 64;  // global col
            if (!(col >= left && col < right)) rowp[col] = swg[lane];
        }
    }

    // phase 2: ctx register tile (8 t's per warp, stream V rows once)
    float a0[8], a1[8];
#pragma unroll
    for (int it = 0; it < 8; it++) { a0[it] = 0.f; a1[it] = 0.f; }

    const float* swlb = &sm[SWL + wid * 320];
    const float* swgb = &sm[SWG + wid * 256];
#pragma unroll 4
    for (int j = 0; j < 40; j++) {
        int r = wid * 8 + j;
        float2 v2 = *(float2*)&sm[SV + r * KVS + 2 * lane];
#pragma unroll
        for (int it = 0; it < 8; it++) {
            float w = swlb[it * 40 + j];
            a0[it] += w * v2.x;
            a1[it] += w * v2.y;
        }
    }
#pragma unroll 4
    for (int g = 0; g < 32; g++) {
        float2 v2 = *(float2*)&sm[SV + (96 + g) * KVS + 2 * lane];
#pragma unroll
        for (int it = 0; it < 8; it++) {
            float w = swgb[it * 32 + g];
            a0[it] += w * v2.x;
            a1[it] += w * v2.y;
        }
    }

#pragma unroll
    for (int it = 0; it < 8; it++) {
        int t = t0 + wid * 8 + it;
        size_t co = ((size_t)t * DIM + h * HD) / 2 + lane;
        ((__half2*)CF)[co] = __floats2half2_rn(a0[it], a1[it]);
    }
}

// ---------------- kernel_launch ----------------
extern "C" void kernel_launch(void* const* d_in, const int* in_sizes, int n_in,
                              void* d_out, int out_size) {
    const float* x  = (const float*)d_in[0];
    const float* Wq = (const float*)d_in[1];
    const float* Wk = (const float*)d_in[2];
    const float* Wv = (const float*)d_in[3];
    const float* Wo = (const float*)d_in[4];

    float* out  = (float*)d_out;
    float* full = (float*)d_out + (size_t)TT * DIM;

    float *Q, *Kb, *V;
    cudaGetSymbolAddress((void**)&Q,  g_Q);
    cudaGetSymbolAddress((void**)&Kb, g_K);
    cudaGetSymbolAddress((void**)&V,  g_V);
    __half *xf, *wf, *cf;
    cudaGetSymbolAddress((void**)&xf, g_xf);
    cudaGetSymbolAddress((void**)&wf, g_wf);
    cudaGetSymbolAddress((void**)&cf, g_cf);

    cudaFuncSetAttribute(gemm_f16, cudaFuncAttributeMaxDynamicSharedMemorySize, GS16);
    cudaFuncSetAttribute(attn_kernel, cudaFuncAttributeMaxDynamicSharedMemorySize, ATT_SMEM);

    // conversions
    {
        int n4x = TT * DIM / 4;
        conv_f16<<<(n4x + 255) / 256, 256>>>(x, xf, n4x);
        dim3 gw(DIM * DIM / 4 / 256, 4);
        conv_w_f16<<<gw, 256>>>(Wq, Wk, Wv, Wo, wf);
    }

    // fused QKV projection + RoPE (fp16 single product)
    {
        dim3 gg(3 * DIM / 128, TT / 128);  // (24, 16)
        gemm_f16<<<gg, 256, GS16>>>(xf, wf, Q, Kb, V, 1);
    }

    // tiled attention (zeroes + scatters `full`, writes ctx fp16)
    {
        dim3 ga(TT / 64, NH);  // (32, 16)
        attn_kernel<<<ga, 256, ATT_SMEM>>>(Q, Kb, V, cf, full);
    }

    // output projection (fp16 single product)
    {
        dim3 gg(DIM / 128, TT / 128);  // (8, 16)
        gemm_f16<<<gg, 256, GS16>>>(cf, wf + 3 * (size_t)DIM * DIM, out, out, out, 0);
    }
}

// round 17
// speedup vs baseline: 1.1542x; 1.0243x over previous
#include <cuda_runtime.h>
#include <cuda_bf16.h>
#include <cuda_fp16.h>
#include <math.h>
#include <cstdint>

#define TT 2048
#define DIM 1024
#define NH 16
#define HD 64
#define WIN 16
#define KS 33
#define NG 32
#define NKEY (KS + NG)

// ---------------- scratch (device globals, no allocation) ----------------
__device__ float g_Q[TT * DIM];
__device__ float g_K[TT * DIM];
__device__ float g_V[TT * DIM];
__device__ __half g_xf[TT * DIM];
__device__ __half g_wf[4 * DIM * DIM];
__device__ __half g_cf[TT * DIM];

// ---------------- PTX helpers (sm_80-generic only) ----------------
__device__ __forceinline__ uint32_t s2u(const void* p) {
    uint32_t a;
    asm("{ .reg .u64 t; cvta.to.shared.u64 t, %1; cvt.u32.u64 %0, t; }" : "=r"(a) : "l"(p));
    return a;
}
__device__ __forceinline__ void cp16(uint32_t saddr, const void* g) {
    asm volatile("cp.async.cg.shared.global [%0], [%1], 16;" :: "r"(saddr), "l"(g));
}
__device__ __forceinline__ void cp_commit() {
    asm volatile("cp.async.commit_group;" ::: "memory");
}
template <int N>
__device__ __forceinline__ void cp_wait() {
    asm volatile("cp.async.wait_group %0;" :: "n"(N) : "memory");
}
__device__ __forceinline__ void ldsm4(uint32_t* r, uint32_t a) {
    asm volatile("ldmatrix.sync.aligned.m8n8.x4.shared.b16 {%0,%1,%2,%3}, [%4];"
                 : "=r"(r[0]), "=r"(r[1]), "=r"(r[2]), "=r"(r[3]) : "r"(a));
}
__device__ __forceinline__ void mma_fp16(float* c, const uint32_t* a, const uint32_t* b) {
    asm volatile(
        "mma.sync.aligned.m16n8k16.row.col.f32.f16.f16.f32 "
        "{%0,%1,%2,%3}, {%4,%5,%6,%7}, {%8,%9}, {%0,%1,%2,%3};"
        : "+f"(c[0]), "+f"(c[1]), "+f"(c[2]), "+f"(c[3])
        : "r"(a[0]), "r"(a[1]), "r"(a[2]), "r"(a[3]), "r"(b[0]), "r"(b[1]));
}

// ---------------- unified fp32 -> fp16 conversion (x + 4 weights) ----------------
// 6 uniform slabs of 262144 float4: y=0,1 -> x halves; y=2..5 -> Wq,Wk,Wv,Wo
__global__ void conv_all(const float* __restrict__ x,
                         const float* __restrict__ W0, const float* __restrict__ W1,
                         const float* __restrict__ W2, const float* __restrict__ W3,
                         __half* __restrict__ xf, __half* __restrict__ wf) {
    const int y = blockIdx.y;
    const int i = blockIdx.x * blockDim.x + threadIdx.x;  // 0..262143
    const float* src;
    __half2* dst;
    if (y < 2) {
        src = x + (size_t)y * 1048576;
        dst = (__half2*)xf + (size_t)y * 524288;
    } else {
        const float* Ws[4] = {W0, W1, W2, W3};
        src = Ws[y - 2];
        dst = (__half2*)wf + (size_t)(y - 2) * 524288;
    }
    float4 v = ((const float4*)src)[i];
    dst[2 * i] = __floats2half2_rn(v.x, v.y);
    dst[2 * i + 1] = __floats2half2_rn(v.z, v.w);
}

// ---------------- fp16 HMMA GEMM: 4 warps x (64x64), 3-stage, fused RoPE ----------------
#define BK 32
#define NCH (DIM / BK)
#define RB16 80
#define T16 (128 * RB16)     // 10240 bytes per operand tile
#define STG16 (2 * T16)      // 20480 bytes per stage
#define GS16 (3 * STG16)     // 61440

__global__ __launch_bounds__(128) void gemm_f16(
    const __half* __restrict__ Af, const __half* __restrict__ Bf,
    float* __restrict__ C0, float* __restrict__ C1, float* __restrict__ C2,
    int doRope) {
    extern __shared__ __align__(128) char smem[];
    const int tid = threadIdx.x;
    const int wid = tid >> 5, lane = tid & 31;
    const int row0 = blockIdx.y * 128, col0 = blockIdx.x * 128;
    const int wm = (wid & 1) * 64, wn = (wid >> 1) * 64;
    const uint32_t sb = s2u(smem);
    const int lr = tid >> 2, lsg = tid & 3;  // lr 0..31, 4 x 16B segments per 64B row

#define LOAD16(c, s)                                                               \
    {                                                                              \
        uint32_t st_ = sb + (s) * STG16;                                           \
        _Pragma("unroll") for (int m_ = 0; m_ < 2; m_++) {                         \
            const __half* src_ = m_ ? Bf : Af;                                     \
            int rbase_ = m_ ? col0 : row0;                                         \
            _Pragma("unroll") for (int r_ = 0; r_ < 4; r_++) {                     \
                int row_ = lr + 32 * r_;                                           \
                const char* g_ = (const char*)(src_ +                              \
                    (size_t)(rbase_ + row_) * DIM + (c) * BK + lsg * 8);           \
                cp16(st_ + m_ * T16 + row_ * RB16 + lsg * 16, g_);                 \
            }                                                                      \
        }                                                                          \
    }

    float acc[4][8][4];
#pragma unroll
    for (int i = 0; i < 4; i++)
#pragma unroll
        for (int j = 0; j < 8; j++)
#pragma unroll
            for (int u = 0; u < 4; u++) acc[i][j][u] = 0.f;

    LOAD16(0, 0); cp_commit();
    LOAD16(1, 1); cp_commit();

    const int ar = lane & 15, ac = lane >> 4;
    const int br = lane & 7, bks = (lane >> 3) & 1, bjj = (lane >> 4) & 1;

    int slot = 0;
    for (int c = 0; c < NCH; c++) {
        if (c < NCH - 1) cp_wait<1>(); else cp_wait<0>();
        __syncthreads();
        if (c + 2 < NCH) {
            int ns = slot + 2; if (ns >= 3) ns -= 3;
            LOAD16(c + 2, ns);
            cp_commit();
        }

        uint32_t st = sb + slot * STG16;
#pragma unroll
        for (int ks = 0; ks < 2; ks++) {
            uint32_t a[4][4];
#pragma unroll
            for (int i = 0; i < 4; i++) {
                uint32_t ad = st + (uint32_t)((wm + i * 16 + ar) * RB16 + (ks * 2 + ac) * 16);
                ldsm4(a[i], ad);
            }
            uint32_t b[4][4];
#pragma unroll
            for (int j2 = 0; j2 < 4; j2++) {
                uint32_t bd = st + T16 +
                              (uint32_t)((wn + j2 * 16 + bjj * 8 + br) * RB16 + (ks * 2 + bks) * 16);
                ldsm4(b[j2], bd);
            }
#pragma unroll
            for (int i = 0; i < 4; i++)
#pragma unroll
                for (int j = 0; j < 8; j++)
                    mma_fp16(acc[i][j], a[i], &b[j >> 1][(j & 1) * 2]);
        }
        slot++; if (slot == 3) slot = 0;
    }

    // epilogue: route by matrix, optional rope, fp32 float2 stores
    const int mat = col0 >> 10;
    float* Cm = (mat == 0) ? C0 : ((mat == 1) ? C1 : C2);
    const bool rope = (doRope != 0) && (mat < 2);
    const int colbase = (col0 & 1023) + wn;
#pragma unroll
    for (int j = 0; j < 8; j++) {
        int colm = colbase + j * 8 + (lane & 3) * 2;
        float invf = 0.f;
        if (rope) {
            int ip = (colm & 63) >> 1;
            invf = powf(10000.0f, -(float)ip * (1.0f / 32.0f));
        }
#pragma unroll
        for (int i = 0; i < 4; i++) {
            int row = row0 + wm + i * 16 + (lane >> 2);
            float2 v0 = {acc[i][j][0], acc[i][j][1]};
            float2 v1 = {acc[i][j][2], acc[i][j][3]};
            if (rope) {
                float s, cc;
                sincosf((float)row * invf, &s, &cc);
                v0 = {v0.x * cc - v0.y * s, v0.x * s + v0.y * cc};
                sincosf((float)(row + 8) * invf, &s, &cc);
                v1 = {v1.x * cc - v1.y * s, v1.x * s + v1.y * cc};
            }
            *(float2*)(Cm + (size_t)row * DIM + colm) = v0;
            *(float2*)(Cm + (size_t)(row + 8) * DIM + colm) = v1;
        }
    }
#undef LOAD16
}

// ---------------- tiled attention: per-it zeroing + atomic-free folded scatter ----------------
#define KVS 68
#define SK 0
#define SV (128 * KVS)                  // 8704
#define SQ (SV + 128 * KVS)             // 17408
#define SWL (SQ + 64 * 64)              // 21504  (8 warps x 8 it x 40 diagonal slots)
#define SWG (SWL + 8 * 8 * 40)          // 24064  (8 warps x 8 it x 32 global slots)
#define ATT_FLOATS (SWG + 8 * 8 * 32)   // 26112
#define ATT_SMEM (ATT_FLOATS * 4)       // 104448 bytes

__global__ __launch_bounds__(256) void attn_kernel(const float* __restrict__ Q,
                                                   const float* __restrict__ K,
                                                   const float* __restrict__ V,
                                                   __half* __restrict__ CF,
                                                   float* __restrict__ full) {
    extern __shared__ float sm[];
    const int tid = threadIdx.x;
    const int wid = tid >> 5, lane = tid & 31;
    const int t0 = blockIdx.x * 64;
    const int h = blockIdx.y;

    // load K/V rows: 0..95 = window [t0-16, t0+79], 96..127 = globals
#pragma unroll
    for (int pass = 0; pass < 8; pass++) {
        int task = tid + pass * 256;
        int r = task >> 4;
        int c4 = task & 15;
        int p = (r < 96) ? (t0 - WIN + r) : ((r - 96) * 64);
        float4 kv = {0.f, 0.f, 0.f, 0.f}, vv = {0.f, 0.f, 0.f, 0.f};
        if (p >= 0 && p < TT) {
            kv = *(const float4*)(K + (size_t)p * DIM + h * HD + c4 * 4);
            vv = *(const float4*)(V + (size_t)p * DIM + h * HD + c4 * 4);
        }
        *(float4*)&sm[SK + r * KVS + c4 * 4] = kv;
        *(float4*)&sm[SV + r * KVS + c4 * 4] = vv;
    }
    // load Q rows
#pragma unroll
    for (int pass = 0; pass < 4; pass++) {
        int task = tid + pass * 256;
        int tt = task >> 4;
        int c4 = task & 15;
        *(float4*)&sm[SQ + tt * 64 + c4 * 4] =
            *(const float4*)(Q + (size_t)(t0 + tt) * DIM + h * HD + c4 * 4);
    }
    __syncthreads();

    // phase 1: per-it zero + scores + softmax + atomic-free folded scatter
    for (int it = 0; it < 8; it++) {
        const int trel = wid * 8 + it;
        const int t = t0 + trel;
        float* rowp = full + ((size_t)h * TT + t) * TT;

        // zero this row (dependency-free float4 stream; interleaves with compute below)
        float4 z4 = {0.f, 0.f, 0.f, 0.f};
#pragma unroll
        for (int z = 0; z < 16; z++) *(float4*)(rowp + (z * 32 + lane) * 4) = z4;

        int rowi[3];
        bool have[3];
        float sc[3] = {0.f, 0.f, 0.f};
#pragma unroll
        for (int u = 0; u < 3; u++) {
            int kk = u * 32 + lane;
            have[u] = (kk < NKEY);
            int r = (kk < KS) ? (trel + kk) : (96 + kk - KS);
            rowi[u] = have[u] ? r : 0;
        }
#pragma unroll
        for (int j = 0; j < 16; j++) {
            float4 q4 = *(float4*)&sm[SQ + trel * 64 + j * 4];
#pragma unroll
            for (int u = 0; u < 3; u++) {
                float4 kv = *(float4*)&sm[SK + rowi[u] * KVS + j * 4];
                sc[u] += kv.x * q4.x + kv.y * q4.y + kv.z * q4.z + kv.w * q4.w;
            }
        }
        float s0 = have[0] ? sc[0] * 0.125f : -1e30f;
        float s1 = have[1] ? sc[1] * 0.125f : -1e30f;
        float s2 = have[2] ? sc[2] * 0.125f : -1e30f;

        float m = fmaxf(fmaxf(s0, s1), s2);
#pragma unroll
        for (int o = 16; o > 0; o >>= 1) m = fmaxf(m, __shfl_xor_sync(0xFFFFFFFFu, m, o));
        float e0 = expf(s0 - m), e1 = expf(s1 - m), e2 = expf(s2 - m);
        float sum = e0 + e1 + e2;
#pragma unroll
        for (int o = 16; o > 0; o >>= 1) sum += __shfl_xor_sync(0xFFFFFFFFu, sum, o);
        const float inv = 1.f / sum;

        // weights to smem: diagonal local layout (for ctx) + global array
        float* swl = &sm[SWL + wid * 320 + it * 40];
        float* swg = &sm[SWG + wid * 256 + it * 32];
        if (lane < 40) swl[lane] = 0.f;
        if (lane < 8) swl[lane + 32] = 0.f;
        __syncwarp();
        float ee[3] = {e0, e1, e2};
#pragma unroll
        for (int u = 0; u < 3; u++) {
            int kk = u * 32 + lane;
            if (kk < NKEY) {
                float w = ee[u] * inv;
                if (kk < KS) swl[it + kk] = w;
                else swg[kk - KS] = w;
            }
        }
        __syncwarp();

        // scatter: warp owns row (h,t); fold global into overlapping local col
        const int left = max(t - WIN, 0);
        const int right = min(t + WIN + 1, TT);
#pragma unroll
        for (int u = 0; u < 2; u++) {
            int kk = u * 32 + lane;
            if (kk < KS) {
                int col = left + kk;
                if (col < right) {
                    float w = swl[it + kk];
                    if ((col & 63) == 0) w += swg[col >> 6];
                    rowp[col] = w;
                }
            }
        }
        {
            int col = lane * 64;  // global col
            if (!(col >= left && col < right)) rowp[col] = swg[lane];
        }
    }

    // phase 2: ctx register tile (8 t's per warp, stream V rows once)
    float a0[8], a1[8];
#pragma unroll
    for (int it = 0; it < 8; it++) { a0[it] = 0.f; a1[it] = 0.f; }

    const float* swlb = &sm[SWL + wid * 320];
    const float* swgb = &sm[SWG + wid * 256];
#pragma unroll 4
    for (int j = 0; j < 40; j++) {
        int r = wid * 8 + j;
        float2 v2 = *(float2*)&sm[SV + r * KVS + 2 * lane];
#pragma unroll
        for (int it = 0; it < 8; it++) {
            float w = swlb[it * 40 + j];
            a0[it] += w * v2.x;
            a1[it] += w * v2.y;
        }
    }
#pragma unroll 4
    for (int g = 0; g < 32; g++) {
        float2 v2 = *(float2*)&sm[SV + (96 + g) * KVS + 2 * lane];
#pragma unroll
        for (int it = 0; it < 8; it++) {
            float w = swgb[it * 32 + g];
            a0[it] += w * v2.x;
            a1[it] += w * v2.y;
        }
    }

#pragma unroll
    for (int it = 0; it < 8; it++) {
        int t = t0 + wid * 8 + it;
        size_t co = ((size_t)t * DIM + h * HD) / 2 + lane;
        ((__half2*)CF)[co] = __floats2half2_rn(a0[it], a1[it]);
    }
}

// ---------------- kernel_launch ----------------
extern "C" void kernel_launch(void* const* d_in, const int* in_sizes, int n_in,
                              void* d_out, int out_size) {
    const float* x  = (const float*)d_in[0];
    const float* Wq = (const float*)d_in[1];
    const float* Wk = (const float*)d_in[2];
    const float* Wv = (const float*)d_in[3];
    const float* Wo = (const float*)d_in[4];

    float* out  = (float*)d_out;
    float* full = (float*)d_out + (size_t)TT * DIM;

    float *Q, *Kb, *V;
    cudaGetSymbolAddress((void**)&Q,  g_Q);
    cudaGetSymbolAddress((void**)&Kb, g_K);
    cudaGetSymbolAddress((void**)&V,  g_V);
    __half *xf, *wf, *cf;
    cudaGetSymbolAddress((void**)&xf, g_xf);
    cudaGetSymbolAddress((void**)&wf, g_wf);
    cudaGetSymbolAddress((void**)&cf, g_cf);

    cudaFuncSetAttribute(gemm_f16, cudaFuncAttributeMaxDynamicSharedMemorySize, GS16);
    cudaFuncSetAttribute(attn_kernel, cudaFuncAttributeMaxDynamicSharedMemorySize, ATT_SMEM);

    // unified conversions (x + all 4 weights)
    {
        dim3 gc(1024, 6);
        conv_all<<<gc, 256>>>(x, Wq, Wk, Wv, Wo, xf, wf);
    }

    // fused QKV projection + RoPE (fp16 single product)
    {
        dim3 gg(3 * DIM / 128, TT / 128);  // (24, 16)
        gemm_f16<<<gg, 128, GS16>>>(xf, wf, Q, Kb, V, 1);
    }

    // tiled attention (zeroes + scatters `full`, writes ctx fp16)
    {
        dim3 ga(TT / 64, NH);  // (32, 16)
        attn_kernel<<<ga, 256, ATT_SMEM>>>(Q, Kb, V, cf, full);
    }

    // output projection (fp16 single product)
    {
        dim3 gg(DIM / 128, TT / 128);  // (8, 16)
        gemm_f16<<<gg, 128, GS16>>>(cf, wf + 3 * (size_t)DIM * DIM, out, out, out, 0);
    }
}